// round 2
// baseline (speedup 1.0000x reference)
#include <cuda_runtime.h>
#include <cstdint>

#define B_   64
#define T_   512
#define D_   256
#define H_   256
#define G4_  1024
#define M_   (B_ * T_)   // 32768

// ---------------- scratch (device globals; no allocations allowed) ----------
__device__ float g_xg[(size_t)M_ * G4_];      // [B][T][4H] gate preacts (128MB)
__device__ float g_y1[(size_t)B_ * T_ * H_];  // layer-1 output (32MB)
__device__ float g_masks[6][B_ * H_];         // [layer*3 + {out,h,c}][B*H]

// ---------------- threefry2x32 (exact JAX implementation) -------------------
__device__ __forceinline__ void threefry2x32(uint32_t k0, uint32_t k1,
                                             uint32_t x0, uint32_t x1,
                                             uint32_t& o0, uint32_t& o1) {
  uint32_t ks2 = k0 ^ k1 ^ 0x1BD11BDAu;
#define TF_R(rot) { x0 += x1; x1 = (x1 << (rot)) | (x1 >> (32 - (rot))); x1 ^= x0; }
  x0 += k0; x1 += k1;
  TF_R(13) TF_R(15) TF_R(26) TF_R(6)
  x0 += k1;  x1 += ks2 + 1u;
  TF_R(17) TF_R(29) TF_R(16) TF_R(24)
  x0 += ks2; x1 += k0 + 2u;
  TF_R(13) TF_R(15) TF_R(26) TF_R(6)
  x0 += k0;  x1 += k1 + 3u;
  TF_R(17) TF_R(29) TF_R(16) TF_R(24)
  x0 += k1;  x1 += ks2 + 4u;
  TF_R(13) TF_R(15) TF_R(26) TF_R(6)
  x0 += ks2; x1 += k0 + 5u;
#undef TF_R
  o0 = x0; o1 = x1;
}

__device__ __forceinline__ float mask_val(uint32_t bits) {
  // jax.random.uniform: bitcast(0x3f800000 | bits>>9) - 1, then < keep(0.75)
  float u = __uint_as_float(0x3f800000u | (bits >> 9)) - 1.0f;
  return (u < 0.75f) ? (1.0f / 0.75f) : 0.0f;
}

// Modern JAX (threefry_partitionable=True, the default):
//   split(key, n)   -> child i = threefry(key, (0, i))        [fold-like]
//   random_bits(key, 32, shape): elem e -> b1,b2 = threefry(key, (0, e));
//                                bits = b1 ^ b2
__global__ void mask_kernel() {
  int mid   = blockIdx.y;        // 0..5
  int layer = mid / 3, which = mid % 3;
  int e = blockIdx.x * blockDim.x + threadIdx.x;   // 0..16383

  // root = key(42) = (0,42)
  uint32_t Lk0, Lk1;
  threefry2x32(0u, 42u, 0u, (uint32_t)layer, Lk0, Lk1);    // split(root,2)[layer]
  uint32_t mk0, mk1;
  threefry2x32(Lk0, Lk1, 0u, (uint32_t)which, mk0, mk1);   // split(L,3)[which]
  uint32_t b1, b2;
  threefry2x32(mk0, mk1, 0u, (uint32_t)e, b1, b2);
  g_masks[mid][e] = mask_val(b1 ^ b2);
}

// ---------------- input-projection GEMM: Y[m][n] = X[m,:]·W[n,:] + bias -----
// X: [M,256] row-major, W: [1024,256] row-major, Y: [M,1024]
__global__ void __launch_bounds__(256) gemm_xg_kernel(
    const float* __restrict__ X, const float* __restrict__ W,
    const float* __restrict__ bi, const float* __restrict__ bh,
    float* __restrict__ Y) {
  const int K = 256, N = 1024;
  __shared__ float As[32][132];   // [kk][mm], padded
  __shared__ float Bs[32][132];   // [kk][nn], padded
  int bm = blockIdx.y * 128, bn = blockIdx.x * 128;
  int tid = threadIdx.x;
  int tx = tid & 15, ty = tid >> 4;

  float acc[8][8];
#pragma unroll
  for (int i = 0; i < 8; i++)
#pragma unroll
    for (int j = 0; j < 8; j++) acc[i][j] = 0.f;

  for (int k0 = 0; k0 < K; k0 += 32) {
#pragma unroll
    for (int i = 0; i < 4; i++) {
      int idx = tid + i * 256;           // 0..1023 float4 slots (128 rows x 8)
      int row = idx >> 3;
      int kk  = (idx & 7) << 2;
      float4 va = *(const float4*)&X[(size_t)(bm + row) * K + k0 + kk];
      As[kk + 0][row] = va.x; As[kk + 1][row] = va.y;
      As[kk + 2][row] = va.z; As[kk + 3][row] = va.w;
      float4 vb = *(const float4*)&W[(size_t)(bn + row) * K + k0 + kk];
      Bs[kk + 0][row] = vb.x; Bs[kk + 1][row] = vb.y;
      Bs[kk + 2][row] = vb.z; Bs[kk + 3][row] = vb.w;
    }
    __syncthreads();
#pragma unroll
    for (int kk = 0; kk < 32; kk++) {
      float a[8], b[8];
#pragma unroll
      for (int i = 0; i < 8; i++) a[i] = As[kk][ty * 8 + i];
#pragma unroll
      for (int j = 0; j < 8; j++) b[j] = Bs[kk][tx * 8 + j];
#pragma unroll
      for (int i = 0; i < 8; i++)
#pragma unroll
        for (int j = 0; j < 8; j++) acc[i][j] = fmaf(a[i], b[j], acc[i][j]);
    }
    __syncthreads();
  }

  float bias[8];
#pragma unroll
  for (int j = 0; j < 8; j++) {
    int n = bn + tx * 8 + j;
    bias[j] = bi[n] + bh[n];
  }
#pragma unroll
  for (int i = 0; i < 8; i++) {
    size_t base = (size_t)(bm + ty * 8 + i) * N + bn + tx * 8;
    float4 v0 = make_float4(acc[i][0] + bias[0], acc[i][1] + bias[1],
                            acc[i][2] + bias[2], acc[i][3] + bias[3]);
    float4 v1 = make_float4(acc[i][4] + bias[4], acc[i][5] + bias[5],
                            acc[i][6] + bias[6], acc[i][7] + bias[7]);
    *(float4*)&Y[base]     = v0;
    *(float4*)&Y[base + 4] = v1;
  }
}

// ---------------- persistent recurrent LSTM layer ---------------------------
// Cluster of 8 CTAs per 4 batch elements. CTA rank s owns hidden units
// [32s, 32s+32) for all 4 gates (128 weight rows, smem-resident, [k][r] layout).
// Per step: each CTA computes its 128x4 gate block, updates its h/c slice,
// broadcasts masked h to all peers via DSMEM, cluster-syncs.
#define LSTM_SMEM_FLOATS (256 * 129 + 2 * 256 * 4 + 4 * 128 * 4)
#define LSTM_SMEM_BYTES  (LSTM_SMEM_FLOATS * 4)

__global__ void __launch_bounds__(512, 1) __cluster_dims__(8, 1, 1)
lstm_layer_kernel(const float* __restrict__ xg, const float* __restrict__ Whh,
                  const float* __restrict__ mask_out,
                  const float* __restrict__ mask_h,
                  const float* __restrict__ mask_c,
                  float* __restrict__ out) {
  extern __shared__ float smem[];
  float* wT   = smem;                 // [256][129]  (k-major, pad 129)
  float* hbuf = wT + 256 * 129;       // [2][256][4] (k-major x batch)
  float* part = hbuf + 2 * 256 * 4;   // [4][128][4] (kq, row, batch)

  int tid = threadIdx.x;
  uint32_t s;
  asm("mov.u32 %0, %%cluster_ctarank;" : "=r"(s));
  int b_base = (blockIdx.x >> 3) * 4;

  int kq = tid >> 7;          // k-quarter 0..3
  int r  = tid & 127;         // local gate-row 0..127 (gate = r>>5, unit = r&31)
  int grow = ((r >> 5) << 8) + ((int)s << 5) + (r & 31);  // global W_hh row

  // load weight slice transposed into smem (conflict-free on read & store)
  for (int idx = tid; idx < 128 * 256; idx += 512) {
    int rr = idx >> 8;
    int k  = idx & 255;
    int gr = ((rr >> 5) << 8) + ((int)s << 5) + (rr & 31);
    wT[k * 129 + rr] = Whh[(size_t)gr * 256 + k];
  }
  for (int idx = tid; idx < 2 * 256 * 4; idx += 512) hbuf[idx] = 0.f;

  // finalize-role (tid < 128): one (unit u, batch b) pair each
  float c_state = 0.f, mo = 0.f, mh = 0.f, mc = 0.f;
  int u = tid >> 2;
  size_t out_base = 0;
  uint32_t haddr[2][8];
  if (tid < 128) {
    int b = tid & 3;
    int bb = b_base + b;
    int unit = (int)s * 32 + u;
    mo = mask_out[bb * 256 + unit];
    mh = mask_h  [bb * 256 + unit];
    mc = mask_c  [bb * 256 + unit];
    out_base = (size_t)bb * (T_ * H_) + unit;
#pragma unroll
    for (int par = 0; par < 2; par++) {
      uint32_t laddr =
          (uint32_t)__cvta_generic_to_shared(&hbuf[par * 1024 + unit * 4 + b]);
#pragma unroll
      for (int rk = 0; rk < 8; rk++) {
        uint32_t ra;
        asm("mapa.shared::cluster.u32 %0, %1, %2;" : "=r"(ra) : "r"(laddr), "r"(rk));
        haddr[par][rk] = ra;
      }
    }
  }

  asm volatile("barrier.cluster.arrive.aligned;" ::: "memory");
  asm volatile("barrier.cluster.wait.aligned;"   ::: "memory");

  const float* wk = wT + (kq * 64) * 129 + r;
  int par = 0;

  for (int t = 0; t < T_; t++) {
    // prefetch this step's input-projection values (kq==0 threads only)
    float xv0 = 0.f, xv1 = 0.f, xv2 = 0.f, xv3 = 0.f;
    if (kq == 0) {
      const float* xp = xg + ((size_t)b_base * T_ + t) * G4_ + grow;
      xv0 = xp[0];
      xv1 = xp[(size_t)T_ * G4_];
      xv2 = xp[(size_t)2 * T_ * G4_];
      xv3 = xp[(size_t)3 * T_ * G4_];
    }

    // partial dot over this thread's k-quarter (64 k), 4 batches at once
    const float* hb = hbuf + par * 1024 + kq * 256;
    float a0 = xv0, a1 = xv1, a2 = xv2, a3 = xv3;
#pragma unroll 16
    for (int k0 = 0; k0 < 64; k0++) {
      float  w  = wk[k0 * 129];
      float4 h4 = *(const float4*)(hb + k0 * 4);
      a0 = fmaf(w, h4.x, a0);
      a1 = fmaf(w, h4.y, a1);
      a2 = fmaf(w, h4.z, a2);
      a3 = fmaf(w, h4.w, a3);
    }
    *(float4*)&part[(kq * 128 + r) * 4] = make_float4(a0, a1, a2, a3);
    __syncthreads();

    if (tid < 128) {
      int b = tid & 3;
      float gi = 0.f, gf = 0.f, gg = 0.f, go = 0.f;
#pragma unroll
      for (int q2 = 0; q2 < 4; q2++) {
        const float* pp = part + q2 * 512;
        gi += pp[(u)      * 4 + b];
        gf += pp[(32 + u) * 4 + b];
        gg += pp[(64 + u) * 4 + b];
        go += pp[(96 + u) * 4 + b];
      }
      float ig = 1.f / (1.f + __expf(-gi));
      float fg = 1.f / (1.f + __expf(-gf));
      float og = 1.f / (1.f + __expf(-go));
      float gt = tanhf(gg);
      c_state = fg * c_state + ig * gt;
      float h = og * tanhf(c_state);
      c_state *= mc;                            // variational cell mask
      out[out_base + (size_t)t * H_] = h * mo;  // output mask
      float hm = h * mh;                        // carry mask
#pragma unroll
      for (int rk = 0; rk < 8; rk++)
        asm volatile("st.shared::cluster.f32 [%0], %1;"
                     :: "r"(haddr[par ^ 1][rk]), "f"(hm) : "memory");
    }
    asm volatile("barrier.cluster.arrive.aligned;" ::: "memory");
    asm volatile("barrier.cluster.wait.aligned;"   ::: "memory");
    par ^= 1;
  }
}

// ---------------- launcher ---------------------------------------------------
extern "C" void kernel_launch(void* const* d_in, const int* in_sizes, int n_in,
                              void* d_out, int out_size) {
  const float* x     = (const float*)d_in[0];
  const float* W_ih0 = (const float*)d_in[1];
  const float* W_hh0 = (const float*)d_in[2];
  const float* b_ih0 = (const float*)d_in[3];
  const float* b_hh0 = (const float*)d_in[4];
  const float* W_ih1 = (const float*)d_in[5];
  const float* W_hh1 = (const float*)d_in[6];
  const float* b_ih1 = (const float*)d_in[7];
  const float* b_hh1 = (const float*)d_in[8];
  float* out = (float*)d_out;

  float *xg, *y1, *masks;
  cudaGetSymbolAddress((void**)&xg, g_xg);
  cudaGetSymbolAddress((void**)&y1, g_y1);
  cudaGetSymbolAddress((void**)&masks, g_masks);

  cudaFuncSetAttribute(lstm_layer_kernel,
                       cudaFuncAttributeMaxDynamicSharedMemorySize,
                       LSTM_SMEM_BYTES);

  mask_kernel<<<dim3(64, 6), 256>>>();

  gemm_xg_kernel<<<dim3(8, 256), 256>>>(x, W_ih0, b_ih0, b_hh0, xg);
  lstm_layer_kernel<<<128, 512, LSTM_SMEM_BYTES>>>(
      xg, W_hh0, masks + 0 * 16384, masks + 1 * 16384, masks + 2 * 16384, y1);

  gemm_xg_kernel<<<dim3(8, 256), 256>>>(y1, W_ih1, b_ih1, b_hh1, xg);
  lstm_layer_kernel<<<128, 512, LSTM_SMEM_BYTES>>>(
      xg, W_hh1, masks + 3 * 16384, masks + 4 * 16384, masks + 5 * 16384, out);
}